// round 2
// baseline (speedup 1.0000x reference)
#include <cuda_runtime.h>
#include <cuda_bf16.h>
#include <cstdint>

// Problem constants
#define BT 8
#define CT 1024
#define ST 2048          // N*P = 64*32 spatial
#define AT (BT*ST)       // 16384 tokens
#define ET 3
#define HT 4096
#define OT 1024

// ---------------- scratch (device globals: no allocations allowed) ---------
__device__ float g_xt[(size_t)AT * CT];     // 64 MB  [A, C] tokens
__device__ float g_gates[AT * ET];          // gates  [A, E]
__device__ float g_h[(size_t)AT * HT];      // 256 MB [A, H] expert hidden
__device__ float g_acc[(size_t)AT * OT];    // 64 MB  [A, O] accumulated out

// ---------------- helpers --------------------------------------------------
__device__ __forceinline__ uint32_t f2tf(float f) {
    uint32_t r;
    asm("cvt.rna.tf32.f32 %0, %1;" : "=r"(r) : "f"(f));
    return r;
}

__device__ __forceinline__ float gelu_exact(float v) {
    return 0.5f * v * (1.0f + erff(v * 0.70710678118654752440f));
}

__device__ __forceinline__ void mma_tf32(float* d, const uint32_t* a, const uint32_t* b) {
    asm volatile(
        "mma.sync.aligned.m16n8k8.row.col.f32.tf32.tf32.f32 "
        "{%0,%1,%2,%3}, {%4,%5,%6,%7}, {%8,%9}, {%0,%1,%2,%3};\n"
        : "+f"(d[0]), "+f"(d[1]), "+f"(d[2]), "+f"(d[3])
        : "r"(a[0]), "r"(a[1]), "r"(a[2]), "r"(a[3]), "r"(b[0]), "r"(b[1]));
}

__device__ __forceinline__ void cp16(uint32_t saddr, const void* gptr) {
    asm volatile("cp.async.cg.shared.global [%0], [%1], 16;\n" :: "r"(saddr), "l"(gptr));
}

// ---------------- kernel 1: transpose x [B,C,S] -> xt [B*S, C] -------------
__global__ void transpose_in(const float* __restrict__ x) {
    __shared__ float tile[32][33];
    int s0 = blockIdx.x * 32, c0 = blockIdx.y * 32, b = blockIdx.z;
    int tx = threadIdx.x, ty = threadIdx.y;
    const float* xb = x + (size_t)b * CT * ST;
#pragma unroll
    for (int j = 0; j < 32; j += 8)
        tile[ty + j][tx] = xb[(size_t)(c0 + ty + j) * ST + s0 + tx];
    __syncthreads();
    float* xtb = g_xt + (size_t)b * ST * CT;
#pragma unroll
    for (int j = 0; j < 32; j += 8)
        xtb[(size_t)(s0 + ty + j) * CT + c0 + tx] = tile[tx][ty + j];
}

// ---------------- kernel 2: noisy top-2-of-3 router (fp32 exact) -----------
__global__ void router_kernel(const float* __restrict__ Wg, const float* __restrict__ bg,
                              const float* __restrict__ Wn, const float* __restrict__ bn,
                              const float* __restrict__ noise_u) {
    int t = (blockIdx.x * blockDim.x + threadIdx.x) >> 5;
    int lane = threadIdx.x & 31;
    const float* xr = g_xt + (size_t)t * CT;
    float sg0 = 0.f, sg1 = 0.f, sg2 = 0.f, sn0 = 0.f, sn1 = 0.f, sn2 = 0.f;
    for (int c = lane; c < CT; c += 32) {
        float xv = xr[c];
        const float* wg = Wg + c * 3;
        const float* wn = Wn + c * 3;
        sg0 += xv * wg[0]; sg1 += xv * wg[1]; sg2 += xv * wg[2];
        sn0 += xv * wn[0]; sn1 += xv * wn[1]; sn2 += xv * wn[2];
    }
#pragma unroll
    for (int off = 16; off; off >>= 1) {
        sg0 += __shfl_xor_sync(0xffffffffu, sg0, off);
        sg1 += __shfl_xor_sync(0xffffffffu, sg1, off);
        sg2 += __shfl_xor_sync(0xffffffffu, sg2, off);
        sn0 += __shfl_xor_sync(0xffffffffu, sn0, off);
        sn1 += __shfl_xor_sync(0xffffffffu, sn1, off);
        sn2 += __shfl_xor_sync(0xffffffffu, sn2, off);
    }
    if (lane == 0) {
        float lg[3] = {sg0 + bg[0], sg1 + bg[1], sg2 + bg[2]};
        float ln[3] = {sn0 + bn[0], sn1 + bn[1], sn2 + bn[2]};
        // softmax over noise logits
        float m = fmaxf(ln[0], fmaxf(ln[1], ln[2]));
        float e0 = expf(ln[0] - m), e1 = expf(ln[1] - m), e2 = expf(ln[2] - m);
        float Z = e0 + e1 + e2;
        float lo[3];
        lo[0] = lg[0] + noise_u[t * 3 + 0] * (e0 / Z);
        lo[1] = lg[1] + noise_u[t * 3 + 1] * (e1 / Z);
        lo[2] = lg[2] + noise_u[t * 3 + 2] * (e2 / Z);
        // drop the min (ties: later index dropped, matching top_k keep-earlier)
        int mi = 0;
        if (lo[1] <= lo[mi]) mi = 1;
        if (lo[2] <= lo[mi]) mi = 2;
        float mmax = -3.0e38f;
#pragma unroll
        for (int e = 0; e < 3; ++e) if (e != mi) mmax = fmaxf(mmax, lo[e]);
        float gg[3]; float Zk = 0.f;
#pragma unroll
        for (int e = 0; e < 3; ++e) {
            gg[e] = (e == mi) ? 0.f : expf(lo[e] - mmax);
            Zk += gg[e];
        }
        g_gates[t * 3 + 0] = gg[0] / Zk;
        g_gates[t * 3 + 1] = gg[1] / Zk;
        g_gates[t * 3 + 2] = gg[2] / Zk;
    }
}

// ---------------- GEMM: 128x128x16 tiles, mma.sync tf32, cp.async dbl-buf --
// EPI==0: g_h = gelu(g_xt @ Bp + bias)          (M=AT, N=HT, K=CT)
// EPI==1: g_acc (=/+=) gate_e * (g_h @ Bp + b)  (M=AT, N=OT, K=HT)
#define BM 128
#define BN 128
#define BKT 16
#define ASTR 20    // BK + 4 pad: frag bank = (4*row + k) % 32 -> conflict-free
#define BSTR 136   // BN + 8 pad: frag bank = (8*k + n)  % 32 -> conflict-free

template<int EPI>
__global__ __launch_bounds__(256)
void gemm_tf32_kernel(const float* __restrict__ Bp, const float* __restrict__ bias,
                      int N, int K, int e, int first) {
    __shared__ float As[2][BM * ASTR];
    __shared__ float Bs[2][BKT * BSTR];

    const float* Ap = (EPI == 0) ? g_xt : g_h;
    float* Cp = (EPI == 0) ? g_h : g_acc;

    const int tid = threadIdx.x;
    const int lane = tid & 31, warpId = tid >> 5;
    const int wm = warpId & 1, wn = warpId >> 1;
    const int g = lane >> 2, q = lane & 3;
    const int bm = blockIdx.y * BM, bn = blockIdx.x * BN;

    // global/shared load mapping (no bounds checks: all dims divide tiles)
    const int aRow0 = tid >> 2;                    // 0..63
    const int aRow1 = aRow0 + 64;                  // 64..127
    const int aKq = (tid & 3) << 2;                // 0,4,8,12
    const int bK0 = tid >> 5;                      // 0..7
    const int bK1 = bK0 + 8;                       // 8..15
    const int bNq = (tid & 31) << 2;               // 0..124

    const float* aG0 = Ap + (size_t)(bm + aRow0) * K + aKq;
    const float* aG1 = Ap + (size_t)(bm + aRow1) * K + aKq;
    const float* bG0 = Bp + (size_t)bK0 * N + bn + bNq;
    const float* bG1 = Bp + (size_t)bK1 * N + bn + bNq;

    auto loadTile = [&](int kt, int buf) {
        uint32_t s;
        s = (uint32_t)__cvta_generic_to_shared(&As[buf][aRow0 * ASTR + aKq]);
        cp16(s, aG0 + kt * BKT);
        s = (uint32_t)__cvta_generic_to_shared(&As[buf][aRow1 * ASTR + aKq]);
        cp16(s, aG1 + kt * BKT);
        s = (uint32_t)__cvta_generic_to_shared(&Bs[buf][bK0 * BSTR + bNq]);
        cp16(s, bG0 + (size_t)kt * BKT * N);
        s = (uint32_t)__cvta_generic_to_shared(&Bs[buf][bK1 * BSTR + bNq]);
        cp16(s, bG1 + (size_t)kt * BKT * N);
        asm volatile("cp.async.commit_group;\n" ::: "memory");
    };

    float acc[4][4][4] = {};

    const int KT = K / BKT;
    loadTile(0, 0);
    for (int kt = 0; kt < KT; ++kt) {
        const int cur = kt & 1;
        if (kt + 1 < KT) {
            loadTile(kt + 1, cur ^ 1);
            asm volatile("cp.async.wait_group 1;\n" ::: "memory");
        } else {
            asm volatile("cp.async.wait_group 0;\n" ::: "memory");
        }
        __syncthreads();
        const float* Asb = As[cur];
        const float* Bsb = Bs[cur];
#pragma unroll
        for (int ks = 0; ks < 2; ++ks) {
            uint32_t af[4][4], bf[4][2];
            const int kk = ks * 8 + q;
#pragma unroll
            for (int mi = 0; mi < 4; ++mi) {
                int r = wm * 64 + mi * 16 + g;
                af[mi][0] = f2tf(Asb[r * ASTR + kk]);
                af[mi][1] = f2tf(Asb[(r + 8) * ASTR + kk]);
                af[mi][2] = f2tf(Asb[r * ASTR + kk + 4]);
                af[mi][3] = f2tf(Asb[(r + 8) * ASTR + kk + 4]);
            }
#pragma unroll
            for (int ni = 0; ni < 4; ++ni) {
                int c = wn * 32 + ni * 8 + g;
                bf[ni][0] = f2tf(Bsb[kk * BSTR + c]);
                bf[ni][1] = f2tf(Bsb[(kk + 4) * BSTR + c]);
            }
#pragma unroll
            for (int mi = 0; mi < 4; ++mi)
#pragma unroll
                for (int ni = 0; ni < 4; ++ni)
                    mma_tf32(acc[mi][ni], af[mi], bf[ni]);
        }
        __syncthreads();
    }

    // epilogue (float2-vectorized: each fragment owns pairs (c, c+1))
#pragma unroll
    for (int mi = 0; mi < 4; ++mi) {
        int r = bm + wm * 64 + mi * 16 + g;
#pragma unroll
        for (int ni = 0; ni < 4; ++ni) {
            int c = bn + wn * 32 + ni * 8 + 2 * q;
            float2 bb = *(const float2*)(bias + c);
            float2 v0 = make_float2(acc[mi][ni][0] + bb.x, acc[mi][ni][1] + bb.y);
            float2 v1 = make_float2(acc[mi][ni][2] + bb.x, acc[mi][ni][3] + bb.y);
            float2* p0 = (float2*)(Cp + (size_t)r * N + c);
            float2* p1 = (float2*)(Cp + (size_t)(r + 8) * N + c);
            if (EPI == 0) {
                *p0 = make_float2(gelu_exact(v0.x), gelu_exact(v0.y));
                *p1 = make_float2(gelu_exact(v1.x), gelu_exact(v1.y));
            } else {
                float ga = g_gates[r * ET + e];
                float gb = g_gates[(r + 8) * ET + e];
                if (first) {
                    *p0 = make_float2(ga * v0.x, ga * v0.y);
                    *p1 = make_float2(gb * v1.x, gb * v1.y);
                } else {
                    float2 o0 = *p0, o1 = *p1;
                    *p0 = make_float2(o0.x + ga * v0.x, o0.y + ga * v0.y);
                    *p1 = make_float2(o1.x + gb * v1.x, o1.y + gb * v1.y);
                }
            }
        }
    }
}

// ---------------- kernel: g_acc [B*S, O] -> out [B, O, S] ------------------
__global__ void reorder_out(float* __restrict__ out) {
    __shared__ float tile[32][33];
    int o0 = blockIdx.x * 32, s0 = blockIdx.y * 32, b = blockIdx.z;
    int tx = threadIdx.x, ty = threadIdx.y;
    const float* ab = g_acc + (size_t)b * ST * OT;
#pragma unroll
    for (int j = 0; j < 32; j += 8)
        tile[ty + j][tx] = ab[(size_t)(s0 + ty + j) * OT + o0 + tx];
    __syncthreads();
    float* ob = out + (size_t)b * OT * ST;
#pragma unroll
    for (int j = 0; j < 32; j += 8)
        ob[(size_t)(o0 + ty + j) * ST + s0 + tx] = tile[tx][ty + j];
}

// ---------------- launch ---------------------------------------------------
extern "C" void kernel_launch(void* const* d_in, const int* in_sizes, int n_in,
                              void* d_out, int out_size) {
    (void)in_sizes; (void)n_in; (void)out_size;
    const float* x  = (const float*)d_in[0];
    const float* Wg = (const float*)d_in[1];
    const float* bg = (const float*)d_in[2];
    const float* Wn = (const float*)d_in[3];
    const float* bn = (const float*)d_in[4];
    const float* W1 = (const float*)d_in[5];
    const float* b1 = (const float*)d_in[6];
    const float* W2 = (const float*)d_in[7];
    const float* b2 = (const float*)d_in[8];
    const float* nu = (const float*)d_in[9];
    float* out = (float*)d_out;

    dim3 tb(32, 8);
    transpose_in<<<dim3(ST / 32, CT / 32, BT), tb>>>(x);
    router_kernel<<<AT / 8, 256>>>(Wg, bg, Wn, bn, nu);
    for (int e = 0; e < ET; ++e) {
        gemm_tf32_kernel<0><<<dim3(HT / BN, AT / BM), 256>>>(
            W1 + (size_t)e * CT * HT, b1 + (size_t)e * HT, HT, CT, e, 0);
        gemm_tf32_kernel<1><<<dim3(OT / BN, AT / BM), 256>>>(
            W2 + (size_t)e * HT * OT, b2 + (size_t)e * OT, OT, HT, e, e == 0);
    }
    reorder_out<<<dim3(OT / 32, ST / 32, BT), tb>>>(out);
}